// round 10
// baseline (speedup 1.0000x reference)
#include <cuda_runtime.h>
#include <cuda_bf16.h>
#include <mma.h>
#include <cstdint>

using namespace nvcuda;

// Problem constants
#define B_IMG   64
#define N_OBJ   64
#define M_EDGE  32768
#define OBJDIM  2048
#define QDIM    1024
#define KS      8
#define HID     512
#define HIDKS   4096
#define N2TILES 128                              // GEMM2 N-tiles (width 32)

// Scratch (device globals; no cudaMalloc allowed)
__device__ __nv_bfloat16 g_nodeB[(size_t)4096 * OBJDIM];
__device__ __nv_bfloat16 g_WobjB[(size_t)OBJDIM * HID];
__device__ __nv_bfloat16 g_qB[(size_t)B_IMG * QDIM];
__device__ __nv_bfloat16 g_WqB[(size_t)QDIM * HIDKS];
__device__ float g_q_h[(size_t)B_IMG * HIDKS];           // [64, 4096]
__device__ float g_P8[(size_t)8 * 4096 * KS];            // per-Ntile P partials
__device__ float g_norm8[(size_t)B_IMG * KS * N2TILES];  // [b][k][ntile]

// ---------------------------------------------------------------------------
__device__ __forceinline__ uint32_t smem_u32(const void* p) {
    uint32_t a;
    asm("{ .reg .u64 t; cvta.to.shared.u64 t, %1; cvt.u32.u64 %0, t; }" : "=r"(a) : "l"(p));
    return a;
}
__device__ __forceinline__ void cp_async16(uint32_t dst, const void* src) {
    asm volatile("cp.async.cg.shared.global [%0], [%1], 16;\n" :: "r"(dst), "l"(src));
}
__device__ __forceinline__ void cp_commit() { asm volatile("cp.async.commit_group;\n"); }
template<int N> __device__ __forceinline__ void cp_wait() {
    asm volatile("cp.async.wait_group %0;\n" :: "n"(N));
}
__device__ __forceinline__ void ldsm_x4(uint32_t& r0, uint32_t& r1, uint32_t& r2,
                                        uint32_t& r3, uint32_t addr) {
    asm volatile("ldmatrix.sync.aligned.m8n8.x4.shared.b16 {%0,%1,%2,%3}, [%4];"
        : "=r"(r0), "=r"(r1), "=r"(r2), "=r"(r3) : "r"(addr));
}
__device__ __forceinline__ void ldsm_x4_t(uint32_t& r0, uint32_t& r1, uint32_t& r2,
                                          uint32_t& r3, uint32_t addr) {
    asm volatile("ldmatrix.sync.aligned.m8n8.x4.trans.shared.b16 {%0,%1,%2,%3}, [%4];"
        : "=r"(r0), "=r"(r1), "=r"(r2), "=r"(r3) : "r"(addr));
}
__device__ __forceinline__ void mma_bf16(float* d, const uint32_t* a,
                                         uint32_t b0, uint32_t b1) {
    asm volatile("mma.sync.aligned.m16n8k16.row.col.f32.bf16.bf16.f32 "
        "{%0,%1,%2,%3}, {%4,%5,%6,%7}, {%8,%9}, {%0,%1,%2,%3};"
        : "+f"(d[0]), "+f"(d[1]), "+f"(d[2]), "+f"(d[3])
        : "r"(a[0]), "r"(a[1]), "r"(a[2]), "r"(a[3]), "r"(b0), "r"(b1));
}

// ---------------------------------------------------------------------------
// Fused fp32 -> bf16 conversion, 32B read / 16B write per thread.
// ---------------------------------------------------------------------------
__global__ __launch_bounds__(256)
void cvt_all_kernel(const float* __restrict__ nf, const float* __restrict__ wo,
                    const float* __restrict__ qf, const float* __restrict__ wq,
                    __nv_bfloat16* __restrict__ nodeB, __nv_bfloat16* __restrict__ wobjB,
                    __nv_bfloat16* __restrict__ qB, __nv_bfloat16* __restrict__ wqB)
{
    const int bid = blockIdx.x;
    const float* src; __nv_bfloat16* dst; int lb;
    if (bid < 4096)      { src = nf; dst = nodeB; lb = bid; }
    else if (bid < 4608) { src = wo; dst = wobjB; lb = bid - 4096; }
    else if (bid < 4640) { src = qf; dst = qB;    lb = bid - 4608; }
    else                 { src = wq; dst = wqB;   lb = bid - 4640; }
    const int i = lb * 256 + threadIdx.x;
    float4 v0 = ((const float4*)src)[i * 2];
    float4 v1 = ((const float4*)src)[i * 2 + 1];
    __nv_bfloat162 o0 = __floats2bfloat162_rn(v0.x, v0.y);
    __nv_bfloat162 o1 = __floats2bfloat162_rn(v0.z, v0.w);
    __nv_bfloat162 o2 = __floats2bfloat162_rn(v1.x, v1.y);
    __nv_bfloat162 o3 = __floats2bfloat162_rn(v1.z, v1.w);
    uint4 pack;
    pack.x = *(uint32_t*)&o0; pack.y = *(uint32_t*)&o1;
    pack.z = *(uint32_t*)&o2; pack.w = *(uint32_t*)&o3;
    ((uint4*)dst)[i] = pack;
}

// ---------------------------------------------------------------------------
// GEMM2: q_h[64,4096] = relu(q_feats @ W_q + b_q), fused norm partials.
// BM=64, BN=32, BK=64, 4 warps, 3-stage pipeline, grid = 128.
// ---------------------------------------------------------------------------
__global__ __launch_bounds__(128)
void gemm2_kernel(const __nv_bfloat16* __restrict__ A, const __nv_bfloat16* __restrict__ Bm,
                  const float* __restrict__ bias, float* __restrict__ C,
                  float* __restrict__ norm8)
{
    constexpr int BM = 64, BN = 32, BK = 64, S = 3;
    constexpr int AP = BK + 8, BP = BN + 8;
    constexpr int STA = BM * AP * 2, STB = BK * BP * 2;
    constexpr int ACH = BM * BK / 8, BCH = BK * BN / 8;
    constexpr int PT = (ACH + BCH) / 128;
    constexpr int NIT = QDIM / BK;
    constexpr int CP = BN + 4;

    extern __shared__ __align__(16) char smem[];
    const uint32_t sA = smem_u32(smem);
    const uint32_t sB = sA + S * STA;

    const int tid = threadIdx.x;
    const int wid = tid >> 5;
    const int wm = wid & 1, wn = wid >> 1;
    const int bN = blockIdx.x * BN;

    auto load_slab = [&](int slab) {
        const int s = slab % S, k0 = slab * BK;
#pragma unroll
        for (int t = 0; t < PT; t++) {
            int l = tid + t * 128;
            if (l < ACH) {
                int r = l >> 3, c = l & 7;
                cp_async16(sA + s * STA + (r * AP + c * 8) * 2,
                           A + (size_t)r * QDIM + k0 + c * 8);
            } else {
                int l2 = l - ACH;
                int r = l2 >> 2, c = l2 & 3;
                cp_async16(sB + s * STB + (r * BP + c * 8) * 2,
                           Bm + (size_t)(k0 + r) * HIDKS + bN + c * 8);
            }
        }
    };

    wmma::fragment<wmma::accumulator, 16, 16, 16, float> acc[2];
#pragma unroll
    for (int f = 0; f < 2; f++) wmma::fill_fragment(acc[f], 0.0f);

#pragma unroll
    for (int s = 0; s < S; s++) { load_slab(s); cp_commit(); }

    for (int i = 0; i < NIT; i++) {
        cp_wait<S - 2>();
        __syncthreads();
        if (i >= 1) {
            int j = i - 1 + S;
            if (j < NIT) load_slab(j);
            cp_commit();
        }
        const __nv_bfloat16* as = (const __nv_bfloat16*)(smem + (size_t)(i % S) * STA);
        const __nv_bfloat16* bs = (const __nv_bfloat16*)(smem + (size_t)S * STA + (size_t)(i % S) * STB);
#pragma unroll
        for (int kk = 0; kk < BK / 16; kk++) {
            wmma::fragment<wmma::matrix_a, 16, 16, 16, __nv_bfloat16, wmma::row_major> af[2];
            wmma::fragment<wmma::matrix_b, 16, 16, 16, __nv_bfloat16, wmma::row_major> bf;
#pragma unroll
            for (int f = 0; f < 2; f++)
                wmma::load_matrix_sync(af[f], as + (wm * 32 + f * 16) * AP + kk * 16, AP);
            wmma::load_matrix_sync(bf, bs + (kk * 16) * BP + wn * 16, BP);
#pragma unroll
            for (int f = 0; f < 2; f++)
                wmma::mma_sync(acc[f], af[f], bf, acc[f]);
        }
    }

    __syncthreads();
    float* Cs = (float*)smem;
    float* biasS = Cs + BM * CP;
#pragma unroll
    for (int f = 0; f < 2; f++)
        wmma::store_matrix_sync(Cs + (wm * 32 + f * 16) * CP + wn * 16,
                                acc[f], CP, wmma::mem_row_major);
    if (tid < BN) biasS[tid] = bias[bN + tid];
    __syncthreads();

#pragma unroll
    for (int t = 0; t < 4; t++) {
        int l = tid + t * 128;
        int r = l >> 3, c4 = (l & 7) * 4;
        float4 v = *(float4*)(Cs + r * CP + c4);
        v.x = fmaxf(v.x + biasS[c4 + 0], 0.0f);
        v.y = fmaxf(v.y + biasS[c4 + 1], 0.0f);
        v.z = fmaxf(v.z + biasS[c4 + 2], 0.0f);
        v.w = fmaxf(v.w + biasS[c4 + 3], 0.0f);
        *(float4*)(C + (size_t)r * HIDKS + bN + c4) = v;
    }
    // Norm partials, layout [b][k][ntile]
    if (tid < BM) {
        float a[KS];
#pragma unroll
        for (int k = 0; k < KS; k++) a[k] = 0.0f;
#pragma unroll
        for (int c = 0; c < BN; c++) {
            float v = fmaxf(Cs[tid * CP + c] + biasS[c], 0.0f);
            a[c & 7] += v * v;
        }
#pragma unroll
        for (int k = 0; k < KS; k++)
            norm8[(size_t)(tid * KS + k) * N2TILES + blockIdx.x] = a[k];
    }
}

// ---------------------------------------------------------------------------
// GEMM1: hand-rolled mma.sync.m16n8k16 + ldmatrix, register double-buffered.
// BM=128, BN=64, BK=64, 8 warps (256 thr), warp tile 32x32 (FM=2 m16, FN=4 n8).
// 3-stage cp.async pipeline; 83 KB smem -> 2 CTAs/SM. Epilogue contracts the
// C tile against q_h into P8 (node_h never hits global memory).
// ---------------------------------------------------------------------------
__global__ __launch_bounds__(256, 2)
void gemm1_kernel(const __nv_bfloat16* __restrict__ A, const __nv_bfloat16* __restrict__ Bm,
                  const float* __restrict__ bias, const float* __restrict__ qh,
                  float* __restrict__ P8)
{
    constexpr int BM = 128, BN = 64, BK = 64, S = 3;
    constexpr int AP = 72, BP = 72;                        // bf16 elems (pad 8)
    constexpr int STA = BM * AP * 2, STB = BK * BP * 2;    // 18432, 9216
    constexpr int ACH = BM * BK / 8, BCH = BK * BN / 8;    // 1024, 512
    constexpr int PT = (ACH + BCH) / 256;                  // 6
    constexpr int NIT = OBJDIM / BK;                       // 32
    constexpr int CP = BN + 4;                             // 68
    constexpr int ROWB = AP * 2;                           // 144 B row stride

    extern __shared__ __align__(16) char smem[];
    const uint32_t sA = smem_u32(smem);
    const uint32_t sB = sA + S * STA;

    const int tid  = threadIdx.x;
    const int wid  = tid >> 5;
    const int lane = tid & 31;
    const int wm = wid & 3, wn = wid >> 2;                 // 4 x 2 warps
    const int bM = blockIdx.y * BM;
    const int bN = blockIdx.x * BN;

    auto load_slab = [&](int slab) {
        const int s = slab % S, k0 = slab * BK;
#pragma unroll
        for (int t = 0; t < PT; t++) {
            int l = tid + t * 256;
            if (l < ACH) {
                int r = l >> 3, c = l & 7;
                cp_async16(sA + s * STA + r * ROWB + c * 16,
                           A + (size_t)(bM + r) * OBJDIM + k0 + c * 8);
            } else {
                int l2 = l - ACH;
                int r = l2 >> 3, c = l2 & 7;
                cp_async16(sB + s * STB + r * ROWB + c * 16,
                           Bm + (size_t)(k0 + r) * HID + bN + c * 8);
            }
        }
    };

    float acc[2][4][4];
#pragma unroll
    for (int f = 0; f < 2; f++)
#pragma unroll
        for (int j = 0; j < 4; j++)
#pragma unroll
            for (int e = 0; e < 4; e++) acc[f][j][e] = 0.0f;

    // lane-constant address parts
    // A tile (f, kk): rows m = wm*32 + f*16 + (lane&15), col-bytes kk*32 + (lane>>4)*16
    const uint32_t aLane = (uint32_t)((wm * 32 + (lane & 15)) * ROWB + (lane >> 4) * 16);
    // B tile (nh, kk): rows k = kk*16 + (lane&15), col-bytes wn*64 + nh*32 + (lane>>4)*16
    const uint32_t bLane = (uint32_t)((lane & 15) * ROWB + wn * 64 + (lane >> 4) * 16);

#pragma unroll
    for (int s = 0; s < S; s++) { load_slab(s); cp_commit(); }

    for (int i = 0; i < NIT; i++) {
        cp_wait<S - 2>();
        __syncthreads();
        if (i >= 1) {
            int j = i - 1 + S;
            if (j < NIT) load_slab(j);
            cp_commit();
        }
        const uint32_t aSt = sA + (i % S) * STA + aLane;
        const uint32_t bSt = sB + (i % S) * STB + bLane;

        uint32_t Ab[2][2][4];     // [buf][f][4]
        uint32_t Bb[2][2][4];     // [buf][nh][4]  (r0=b0 n0-7, r1=b1 n0-7, r2=b0 n8-15, r3=b1 n8-15)
        // kk = 0 into buf 0
        ldsm_x4(Ab[0][0][0], Ab[0][0][1], Ab[0][0][2], Ab[0][0][3], aSt);
        ldsm_x4(Ab[0][1][0], Ab[0][1][1], Ab[0][1][2], Ab[0][1][3], aSt + 16 * ROWB);
        ldsm_x4_t(Bb[0][0][0], Bb[0][0][1], Bb[0][0][2], Bb[0][0][3], bSt);
        ldsm_x4_t(Bb[0][1][0], Bb[0][1][1], Bb[0][1][2], Bb[0][1][3], bSt + 32);
#pragma unroll
        for (int kk = 0; kk < 4; kk++) {
            const int cur = kk & 1, nxt = cur ^ 1;
            if (kk < 3) {
                const uint32_t aN = aSt + (kk + 1) * 32;
                const uint32_t bN2 = bSt + (kk + 1) * 16 * ROWB;
                ldsm_x4(Ab[nxt][0][0], Ab[nxt][0][1], Ab[nxt][0][2], Ab[nxt][0][3], aN);
                ldsm_x4(Ab[nxt][1][0], Ab[nxt][1][1], Ab[nxt][1][2], Ab[nxt][1][3], aN + 16 * ROWB);
                ldsm_x4_t(Bb[nxt][0][0], Bb[nxt][0][1], Bb[nxt][0][2], Bb[nxt][0][3], bN2);
                ldsm_x4_t(Bb[nxt][1][0], Bb[nxt][1][1], Bb[nxt][1][2], Bb[nxt][1][3], bN2 + 32);
            }
#pragma unroll
            for (int f = 0; f < 2; f++) {
                mma_bf16(acc[f][0], Ab[cur][f], Bb[cur][0][0], Bb[cur][0][1]);
                mma_bf16(acc[f][1], Ab[cur][f], Bb[cur][0][2], Bb[cur][0][3]);
                mma_bf16(acc[f][2], Ab[cur][f], Bb[cur][1][0], Bb[cur][1][1]);
                mma_bf16(acc[f][3], Ab[cur][f], Bb[cur][1][2], Bb[cur][1][3]);
            }
        }
    }

    // Epilogue: acc -> Cs, then contract vs q_h into P8 (exclusive writes)
    __syncthreads();
    float* Cs    = (float*)smem;                 // 128 x 68 = 34816 B
    float* qs    = Cs + BM * CP;                 // 1024 floats
    float* biasS = qs + 1024;                    // 64 floats
#pragma unroll
    for (int f = 0; f < 2; f++)
#pragma unroll
        for (int j = 0; j < 4; j++) {
            const int row = wm * 32 + f * 16 + (lane >> 2);
            const int col = wn * 32 + j * 8 + (lane & 3) * 2;
            *(float2*)(Cs + row * CP + col)       = make_float2(acc[f][j][0], acc[f][j][1]);
            *(float2*)(Cs + (row + 8) * CP + col) = make_float2(acc[f][j][2], acc[f][j][3]);
        }
    {   // stage q_h segments for the two batches covered by this M-tile
        const int bB0 = bM >> 6;
        const int s = tid >> 7, i4 = (tid & 127) * 4;
        *(float4*)(qs + s * 512 + i4) =
            *(const float4*)(qh + (size_t)(bB0 + s) * HIDKS + bN * KS + i4);
        if (tid < BN) biasS[tid] = bias[bN + tid];
    }
    __syncthreads();

    // 2 threads per row, 32 cols each; combine via shfl
    const int r = tid >> 1;
    const int ch = (tid & 1) * 32;
    const float* qsp = qs + (r >> 6) * 512;
    float a[KS];
#pragma unroll
    for (int k = 0; k < KS; k++) a[k] = 0.0f;
#pragma unroll 8
    for (int cc = 0; cc < 32; cc++) {
        const int c = ch + cc;
        float v = fmaxf(Cs[r * CP + c] + biasS[c], 0.0f);
        float4 q0 = *(const float4*)(qsp + c * 8);
        float4 q1 = *(const float4*)(qsp + c * 8 + 4);
        a[0] += v * q0.x; a[1] += v * q0.y; a[2] += v * q0.z; a[3] += v * q0.w;
        a[4] += v * q1.x; a[5] += v * q1.y; a[6] += v * q1.z; a[7] += v * q1.w;
    }
#pragma unroll
    for (int k = 0; k < KS; k++)
        a[k] += __shfl_xor_sync(0xFFFFFFFFu, a[k], 1);
    if ((tid & 1) == 0) {
        float* dst = P8 + (size_t)blockIdx.x * (4096 * KS) + (size_t)(bM + r) * KS;
        *(float4*)dst       = make_float4(a[0], a[1], a[2], a[3]);
        *(float4*)(dst + 4) = make_float4(a[4], a[5], a[6], a[7]);
    }
}

// ---------------------------------------------------------------------------
// Fused finalize + gather: one block per batch (64 blocks, 256 threads).
// ---------------------------------------------------------------------------
__global__ __launch_bounds__(256)
void finalize_gather_kernel(const int* __restrict__ idxs, const float* __restrict__ P8,
                            const float* __restrict__ norm8, float* __restrict__ out)
{
    __shared__ float Ps[N_OBJ * KS];             // 512 floats
    __shared__ float normS[KS * 16];
    __shared__ float invS[KS];
    const int b   = blockIdx.x;
    const int tid = threadIdx.x;

    if (tid < 128) {
        // each thread one float4 of P: 8 partials at 32KB stride (MLP=8)
        const float4* src = (const float4*)P8;
        const int base = b * N_OBJ * 2;
        float4 s = make_float4(0.f, 0.f, 0.f, 0.f);
#pragma unroll
        for (int nt = 0; nt < 8; nt++) {
            float4 v = src[nt * 8192 + base + tid];
            s.x += v.x; s.y += v.y; s.z += v.z; s.w += v.w;
        }
        ((float4*)Ps)[tid] = s;
    } else {
        // norm8 layout [b][k][nt]: 16 threads per k, 8 contiguous floats each
        const int t = tid - 128;
        const int k = t >> 4, j = t & 15;
        const float4* src = (const float4*)(norm8 + (size_t)(b * KS + k) * N2TILES + j * 8);
        float4 v0 = src[0], v1 = src[1];
        normS[k * 16 + j] = v0.x + v0.y + v0.z + v0.w + v1.x + v1.y + v1.z + v1.w;
    }
    __syncthreads();
    if (tid < KS) {
        float s = 0.f;
#pragma unroll
        for (int p = 0; p < 16; p++) s += normS[tid * 16 + p];
        invS[tid] = rsqrtf(s);
    }
    __syncthreads();

    const float4 i0 = *(const float4*)invS;
    const float4 i1 = *(const float4*)(invS + 4);
#pragma unroll
    for (int e = 0; e < 2; e++) {
        const int m = b * 512 + tid + e * 256;
        const int idx = __ldg(idxs + m);
        const int rem = idx & 4095;
        const int src = rem >> 6, dst = rem & 63;
        const float4* ps = (const float4*)(Ps + src * KS);
        const float4* pd = (const float4*)(Ps + dst * KS);
        float4 s0 = ps[0], s1 = ps[1], d0 = pd[0], d1 = pd[1];
        float4 o0 = make_float4((s0.x + d0.x) * i0.x, (s0.y + d0.y) * i0.y,
                                (s0.z + d0.z) * i0.z, (s0.w + d0.w) * i0.w);
        float4 o1 = make_float4((s1.x + d1.x) * i1.x, (s1.y + d1.y) * i1.y,
                                (s1.z + d1.z) * i1.z, (s1.w + d1.w) * i1.w);
        ((float4*)out)[(size_t)m * 2]     = o0;
        ((float4*)out)[(size_t)m * 2 + 1] = o1;
    }
}

// ---------------------------------------------------------------------------
extern "C" void kernel_launch(void* const* d_in, const int* in_sizes, int n_in,
                              void* d_out, int out_size)
{
    const float* node_feats = (const float*)d_in[0];
    const float* q_feats    = (const float*)d_in[1];
    const int*   indexes    = (const int*)d_in[2];
    const float* W_obj      = (const float*)d_in[3];
    const float* b_obj      = (const float*)d_in[4];
    const float* W_q        = (const float*)d_in[5];
    const float* b_q        = (const float*)d_in[6];
    float* out = (float*)d_out;

    __nv_bfloat16 *nodeB, *wobjB, *qB, *wqB;
    float *qh, *P8, *norm8;
    cudaGetSymbolAddress((void**)&nodeB, g_nodeB);
    cudaGetSymbolAddress((void**)&wobjB, g_WobjB);
    cudaGetSymbolAddress((void**)&qB,    g_qB);
    cudaGetSymbolAddress((void**)&wqB,   g_WqB);
    cudaGetSymbolAddress((void**)&qh,    g_q_h);
    cudaGetSymbolAddress((void**)&P8,    g_P8);
    cudaGetSymbolAddress((void**)&norm8, g_norm8);

    // 1) all fp32 -> bf16 conversions, one launch
    cvt_all_kernel<<<6688, 256>>>(node_feats, W_obj, q_feats, W_q,
                                  nodeB, wobjB, qB, wqB);

    // 2) GEMM2 + norm partials (must precede GEMM1: epilogue consumes q_h)
    {
        constexpr int SM = 3 * (64 * 72 * 2 + 64 * 40 * 2);      // 43008
        cudaFuncSetAttribute(gemm2_kernel, cudaFuncAttributeMaxDynamicSharedMemorySize, SM);
        gemm2_kernel<<<N2TILES, 128, SM>>>(qB, wqB, b_q, qh, norm8);
    }
    // 3) GEMM1 (hand-rolled mma.sync) fused with P contraction
    {
        constexpr int SM = 3 * (128 * 72 * 2 + 64 * 72 * 2);     // 82944
        cudaFuncSetAttribute(gemm1_kernel, cudaFuncAttributeMaxDynamicSharedMemorySize, SM);
        gemm1_kernel<<<dim3(HID / 64, 4096 / 128), 256, SM>>>(nodeB, wobjB, b_obj, qh, P8);
    }
    // 4) fused finalize + edge gather (one block per batch)
    finalize_gather_kernel<<<B_IMG, 256>>>(indexes, P8, norm8, out);
}

// round 11
// speedup vs baseline: 1.0059x; 1.0059x over previous
#include <cuda_runtime.h>
#include <cuda_bf16.h>
#include <mma.h>
#include <cstdint>

using namespace nvcuda;

// Problem constants
#define B_IMG   64
#define N_OBJ   64
#define M_EDGE  32768
#define OBJDIM  2048
#define QDIM    1024
#define KS      8
#define HID     512
#define HIDKS   4096
#define N2TILES 128                              // GEMM2 N-tiles (width 32)
#define N1TILES 4                                // GEMM1 N-tiles (width 128)

// Scratch (device globals; no cudaMalloc allowed)
__device__ __nv_bfloat16 g_nodeB[(size_t)4096 * OBJDIM];
__device__ __nv_bfloat16 g_WobjB[(size_t)OBJDIM * HID];
__device__ __nv_bfloat16 g_qB[(size_t)B_IMG * QDIM];
__device__ __nv_bfloat16 g_WqB[(size_t)QDIM * HIDKS];
__device__ float g_q_h[(size_t)B_IMG * HIDKS];           // [64, 4096]
__device__ float g_P4[(size_t)N1TILES * 4096 * KS];      // per-Ntile P partials
__device__ float g_norm8[(size_t)B_IMG * KS * N2TILES];  // [b][k][ntile]

// ---------------------------------------------------------------------------
__device__ __forceinline__ uint32_t smem_u32(const void* p) {
    uint32_t a;
    asm("{ .reg .u64 t; cvta.to.shared.u64 t, %1; cvt.u32.u64 %0, t; }" : "=r"(a) : "l"(p));
    return a;
}
__device__ __forceinline__ void cp_async16(uint32_t dst, const void* src) {
    asm volatile("cp.async.cg.shared.global [%0], [%1], 16;\n" :: "r"(dst), "l"(src));
}
__device__ __forceinline__ void cp_commit() { asm volatile("cp.async.commit_group;\n"); }
template<int N> __device__ __forceinline__ void cp_wait() {
    asm volatile("cp.async.wait_group %0;\n" :: "n"(N));
}
__device__ __forceinline__ void ldsm_x4(uint32_t* r, uint32_t addr) {
    asm volatile("ldmatrix.sync.aligned.m8n8.x4.shared.b16 {%0,%1,%2,%3}, [%4];"
        : "=r"(r[0]), "=r"(r[1]), "=r"(r[2]), "=r"(r[3]) : "r"(addr));
}
__device__ __forceinline__ void ldsm_x4_t(uint32_t* r, uint32_t addr) {
    asm volatile("ldmatrix.sync.aligned.m8n8.x4.trans.shared.b16 {%0,%1,%2,%3}, [%4];"
        : "=r"(r[0]), "=r"(r[1]), "=r"(r[2]), "=r"(r[3]) : "r"(addr));
}
__device__ __forceinline__ void mma_bf16(float* d, const uint32_t* a,
                                         uint32_t b0, uint32_t b1) {
    asm volatile("mma.sync.aligned.m16n8k16.row.col.f32.bf16.bf16.f32 "
        "{%0,%1,%2,%3}, {%4,%5,%6,%7}, {%8,%9}, {%0,%1,%2,%3};"
        : "+f"(d[0]), "+f"(d[1]), "+f"(d[2]), "+f"(d[3])
        : "r"(a[0]), "r"(a[1]), "r"(a[2]), "r"(a[3]), "r"(b0), "r"(b1));
}

// ---------------------------------------------------------------------------
// Fused fp32 -> bf16 conversion, 32B read / 16B write per thread.
// ---------------------------------------------------------------------------
__global__ __launch_bounds__(256)
void cvt_all_kernel(const float* __restrict__ nf, const float* __restrict__ wo,
                    const float* __restrict__ qf, const float* __restrict__ wq,
                    __nv_bfloat16* __restrict__ nodeB, __nv_bfloat16* __restrict__ wobjB,
                    __nv_bfloat16* __restrict__ qB, __nv_bfloat16* __restrict__ wqB)
{
    const int bid = blockIdx.x;
    const float* src; __nv_bfloat16* dst; int lb;
    if (bid < 4096)      { src = nf; dst = nodeB; lb = bid; }
    else if (bid < 4608) { src = wo; dst = wobjB; lb = bid - 4096; }
    else if (bid < 4640) { src = qf; dst = qB;    lb = bid - 4608; }
    else                 { src = wq; dst = wqB;   lb = bid - 4640; }
    const int i = lb * 256 + threadIdx.x;
    float4 v0 = ((const float4*)src)[i * 2];
    float4 v1 = ((const float4*)src)[i * 2 + 1];
    __nv_bfloat162 o0 = __floats2bfloat162_rn(v0.x, v0.y);
    __nv_bfloat162 o1 = __floats2bfloat162_rn(v0.z, v0.w);
    __nv_bfloat162 o2 = __floats2bfloat162_rn(v1.x, v1.y);
    __nv_bfloat162 o3 = __floats2bfloat162_rn(v1.z, v1.w);
    uint4 pack;
    pack.x = *(uint32_t*)&o0; pack.y = *(uint32_t*)&o1;
    pack.z = *(uint32_t*)&o2; pack.w = *(uint32_t*)&o3;
    ((uint4*)dst)[i] = pack;
}

// ---------------------------------------------------------------------------
// GEMM2: q_h[64,4096] = relu(q_feats @ W_q + b_q), fused norm partials.
// BM=64, BN=32, BK=64, 4 warps, 3-stage pipeline, grid = 128.
// ---------------------------------------------------------------------------
__global__ __launch_bounds__(128)
void gemm2_kernel(const __nv_bfloat16* __restrict__ A, const __nv_bfloat16* __restrict__ Bm,
                  const float* __restrict__ bias, float* __restrict__ C,
                  float* __restrict__ norm8)
{
    constexpr int BM = 64, BN = 32, BK = 64, S = 3;
    constexpr int AP = BK + 8, BP = BN + 8;
    constexpr int STA = BM * AP * 2, STB = BK * BP * 2;
    constexpr int ACH = BM * BK / 8, BCH = BK * BN / 8;
    constexpr int PT = (ACH + BCH) / 128;
    constexpr int NIT = QDIM / BK;
    constexpr int CP = BN + 4;

    extern __shared__ __align__(16) char smem[];
    const uint32_t sA = smem_u32(smem);
    const uint32_t sB = sA + S * STA;

    const int tid = threadIdx.x;
    const int wid = tid >> 5;
    const int wm = wid & 1, wn = wid >> 1;
    const int bN = blockIdx.x * BN;

    auto load_slab = [&](int slab) {
        const int s = slab % S, k0 = slab * BK;
#pragma unroll
        for (int t = 0; t < PT; t++) {
            int l = tid + t * 128;
            if (l < ACH) {
                int r = l >> 3, c = l & 7;
                cp_async16(sA + s * STA + (r * AP + c * 8) * 2,
                           A + (size_t)r * QDIM + k0 + c * 8);
            } else {
                int l2 = l - ACH;
                int r = l2 >> 2, c = l2 & 3;
                cp_async16(sB + s * STB + (r * BP + c * 8) * 2,
                           Bm + (size_t)(k0 + r) * HIDKS + bN + c * 8);
            }
        }
    };

    wmma::fragment<wmma::accumulator, 16, 16, 16, float> acc[2];
#pragma unroll
    for (int f = 0; f < 2; f++) wmma::fill_fragment(acc[f], 0.0f);

#pragma unroll
    for (int s = 0; s < S; s++) { load_slab(s); cp_commit(); }

    for (int i = 0; i < NIT; i++) {
        cp_wait<S - 2>();
        __syncthreads();
        if (i >= 1) {
            int j = i - 1 + S;
            if (j < NIT) load_slab(j);
            cp_commit();
        }
        const __nv_bfloat16* as = (const __nv_bfloat16*)(smem + (size_t)(i % S) * STA);
        const __nv_bfloat16* bs = (const __nv_bfloat16*)(smem + (size_t)S * STA + (size_t)(i % S) * STB);
#pragma unroll
        for (int kk = 0; kk < BK / 16; kk++) {
            wmma::fragment<wmma::matrix_a, 16, 16, 16, __nv_bfloat16, wmma::row_major> af[2];
            wmma::fragment<wmma::matrix_b, 16, 16, 16, __nv_bfloat16, wmma::row_major> bf;
#pragma unroll
            for (int f = 0; f < 2; f++)
                wmma::load_matrix_sync(af[f], as + (wm * 32 + f * 16) * AP + kk * 16, AP);
            wmma::load_matrix_sync(bf, bs + (kk * 16) * BP + wn * 16, BP);
#pragma unroll
            for (int f = 0; f < 2; f++)
                wmma::mma_sync(acc[f], af[f], bf, acc[f]);
        }
    }

    __syncthreads();
    float* Cs = (float*)smem;
    float* biasS = Cs + BM * CP;
#pragma unroll
    for (int f = 0; f < 2; f++)
        wmma::store_matrix_sync(Cs + (wm * 32 + f * 16) * CP + wn * 16,
                                acc[f], CP, wmma::mem_row_major);
    if (tid < BN) biasS[tid] = bias[bN + tid];
    __syncthreads();

#pragma unroll
    for (int t = 0; t < 4; t++) {
        int l = tid + t * 128;
        int r = l >> 3, c4 = (l & 7) * 4;
        float4 v = *(float4*)(Cs + r * CP + c4);
        v.x = fmaxf(v.x + biasS[c4 + 0], 0.0f);
        v.y = fmaxf(v.y + biasS[c4 + 1], 0.0f);
        v.z = fmaxf(v.z + biasS[c4 + 2], 0.0f);
        v.w = fmaxf(v.w + biasS[c4 + 3], 0.0f);
        *(float4*)(C + (size_t)r * HIDKS + bN + c4) = v;
    }
    // Norm partials, layout [b][k][ntile]
    if (tid < BM) {
        float a[KS];
#pragma unroll
        for (int k = 0; k < KS; k++) a[k] = 0.0f;
#pragma unroll
        for (int c = 0; c < BN; c++) {
            float v = fmaxf(Cs[tid * CP + c] + biasS[c], 0.0f);
            a[c & 7] += v * v;
        }
#pragma unroll
        for (int k = 0; k < KS; k++)
            norm8[(size_t)(tid * KS + k) * N2TILES + blockIdx.x] = a[k];
    }
}

// ---------------------------------------------------------------------------
// GEMM1: mma.sync.m16n8k16 + ldmatrix. BM=128, BN=128, BK=64, 8 warps,
// warp arrangement 2(m) x 4(n), warp tile 64x32 (FM=4, FN=4 n8-tiles).
// 4-stage cp.async pipeline (143 KB smem, 1 CTA/SM, no reg cap).
// A re-read 4x (vs 8x at BN=64): L2 traffic 192 -> 128 MB.
// Epilogue contracts the 128x128 C tile against q_h into P4.
// ---------------------------------------------------------------------------
__global__ __launch_bounds__(256)
void gemm1_kernel(const __nv_bfloat16* __restrict__ A, const __nv_bfloat16* __restrict__ Bm,
                  const float* __restrict__ bias, const float* __restrict__ qh,
                  float* __restrict__ P4)
{
    constexpr int BM = 128, BN = 128, BK = 64, S = 4;
    constexpr int AP = 72, BP = BN + 8;                    // bf16 elems
    constexpr int RA = AP * 2, RB = BP * 2;                // 144, 272 B row strides
    constexpr int STA = BM * RA, STB = BK * RB;            // 18432, 17408
    constexpr int ACH = BM * BK / 8, BCH = BK * BN / 8;    // 1024, 1024
    constexpr int PT = (ACH + BCH) / 256;                  // 8
    constexpr int NIT = OBJDIM / BK;                       // 32
    constexpr int CP = BN + 4;                             // 132

    extern __shared__ __align__(16) char smem[];
    const uint32_t sA = smem_u32(smem);
    const uint32_t sB = sA + S * STA;

    const int tid  = threadIdx.x;
    const int wid  = tid >> 5;
    const int lane = tid & 31;
    const int wm = wid & 1, wn = wid >> 1;                 // 2 x 4 warps
    const int bM = blockIdx.y * BM;
    const int bN = blockIdx.x * BN;

    auto load_slab = [&](int slab) {
        const int s = slab % S, k0 = slab * BK;
#pragma unroll
        for (int t = 0; t < PT; t++) {
            int l = tid + t * 256;
            if (l < ACH) {
                int r = l >> 3, c = l & 7;
                cp_async16(sA + s * STA + r * RA + c * 16,
                           A + (size_t)(bM + r) * OBJDIM + k0 + c * 8);
            } else {
                int l2 = l - ACH;
                int r = l2 >> 4, c = l2 & 15;
                cp_async16(sB + s * STB + r * RB + c * 16,
                           Bm + (size_t)(k0 + r) * HID + bN + c * 8);
            }
        }
    };

    float acc[4][4][4];                                    // [f m16][j n8][4]
#pragma unroll
    for (int f = 0; f < 4; f++)
#pragma unroll
        for (int j = 0; j < 4; j++)
#pragma unroll
            for (int e = 0; e < 4; e++) acc[f][j][e] = 0.0f;

    // lane-constant address parts
    const uint32_t aLane = (uint32_t)((wm * 64 + (lane & 15)) * RA + (lane >> 4) * 16);
    const uint32_t bLane = (uint32_t)((lane & 15) * RB + wn * 64 + (lane >> 4) * 16);

#pragma unroll
    for (int s = 0; s < S; s++) { load_slab(s); cp_commit(); }

    for (int i = 0; i < NIT; i++) {
        cp_wait<S - 2>();
        __syncthreads();
        if (i >= 1) {
            int j = i - 1 + S;
            if (j < NIT) load_slab(j);
            cp_commit();
        }
        const uint32_t aSt = sA + (i % S) * STA + aLane;
        const uint32_t bSt = sB + (i % S) * STB + bLane;

        uint32_t Ab[2][4][4];     // [buf][f][4]
        uint32_t Bb[2][2][4];     // [buf][nh][4]
#pragma unroll
        for (int f = 0; f < 4; f++) ldsm_x4(Ab[0][f], aSt + f * 16 * RA);
#pragma unroll
        for (int nh = 0; nh < 2; nh++) ldsm_x4_t(Bb[0][nh], bSt + nh * 32);
#pragma unroll
        for (int kk = 0; kk < 4; kk++) {
            const int cur = kk & 1, nxt = cur ^ 1;
            if (kk < 3) {
                const uint32_t aN = aSt + (kk + 1) * 32;
                const uint32_t bN2 = bSt + (kk + 1) * 16 * RB;
#pragma unroll
                for (int f = 0; f < 4; f++) ldsm_x4(Ab[nxt][f], aN + f * 16 * RA);
#pragma unroll
                for (int nh = 0; nh < 2; nh++) ldsm_x4_t(Bb[nxt][nh], bN2 + nh * 32);
            }
#pragma unroll
            for (int f = 0; f < 4; f++) {
                mma_bf16(acc[f][0], Ab[cur][f], Bb[cur][0][0], Bb[cur][0][1]);
                mma_bf16(acc[f][1], Ab[cur][f], Bb[cur][0][2], Bb[cur][0][3]);
                mma_bf16(acc[f][2], Ab[cur][f], Bb[cur][1][0], Bb[cur][1][1]);
                mma_bf16(acc[f][3], Ab[cur][f], Bb[cur][1][2], Bb[cur][1][3]);
            }
        }
    }

    // Epilogue: acc -> Cs, then contract vs q_h into P4 (exclusive writes)
    __syncthreads();
    float* Cs    = (float*)smem;                 // 128 x 132 x 4 = 67584 B
    float* qs    = Cs + BM * CP;                 // 2048 floats (2 batches x 128c x 8k)
    float* biasS = qs + 2048;                    // 128 floats
#pragma unroll
    for (int f = 0; f < 4; f++)
#pragma unroll
        for (int j = 0; j < 4; j++) {
            const int row = wm * 64 + f * 16 + (lane >> 2);
            const int col = wn * 32 + j * 8 + (lane & 3) * 2;
            *(float2*)(Cs + row * CP + col)       = make_float2(acc[f][j][0], acc[f][j][1]);
            *(float2*)(Cs + (row + 8) * CP + col) = make_float2(acc[f][j][2], acc[f][j][3]);
        }
    {   // stage q_h segments for the two batches covered by this M-tile
        const int bB0 = bM >> 6;
#pragma unroll
        for (int t = 0; t < 2; t++) {
            int idx = tid + t * 256;             // 512 float4 slots
            int s = idx >> 8, i4 = (idx & 255) * 4;
            *(float4*)(qs + s * 1024 + i4) =
                *(const float4*)(qh + (size_t)(bB0 + s) * HIDKS + bN * KS + i4);
        }
        if (tid < BN) biasS[tid] = bias[bN + tid];
    }
    __syncthreads();

    // 2 threads per row, 64 cols each; combine via shfl
    const int r = tid >> 1;
    const int ch = (tid & 1) * 64;
    const float* qsp = qs + (r >> 6) * 1024;
    float a[KS];
#pragma unroll
    for (int k = 0; k < KS; k++) a[k] = 0.0f;
#pragma unroll 8
    for (int cc = 0; cc < 64; cc++) {
        const int c = ch + cc;
        float v = fmaxf(Cs[r * CP + c] + biasS[c], 0.0f);
        float4 q0 = *(const float4*)(qsp + c * 8);
        float4 q1 = *(const float4*)(qsp + c * 8 + 4);
        a[0] += v * q0.x; a[1] += v * q0.y; a[2] += v * q0.z; a[3] += v * q0.w;
        a[4] += v * q1.x; a[5] += v * q1.y; a[6] += v * q1.z; a[7] += v * q1.w;
    }
#pragma unroll
    for (int k = 0; k < KS; k++)
        a[k] += __shfl_xor_sync(0xFFFFFFFFu, a[k], 1);
    if ((tid & 1) == 0) {
        float* dst = P4 + (size_t)blockIdx.x * (4096 * KS) + (size_t)(bM + r) * KS;
        *(float4*)dst       = make_float4(a[0], a[1], a[2], a[3]);
        *(float4*)(dst + 4) = make_float4(a[4], a[5], a[6], a[7]);
    }
}

// ---------------------------------------------------------------------------
// Fused finalize + gather: 4 blocks per batch (256 blocks, 256 threads).
// Each block redundantly reduces its batch's P (4 partials) + norms into smem,
// then emits 128 of the batch's 512 edges.
// ---------------------------------------------------------------------------
__global__ __launch_bounds__(256)
void finalize_gather_kernel(const int* __restrict__ idxs, const float* __restrict__ P4,
                            const float* __restrict__ norm8, float* __restrict__ out)
{
    __shared__ float Ps[N_OBJ * KS];             // 512 floats
    __shared__ float normS[KS * 16];
    __shared__ float invS[KS];
    const int b   = blockIdx.x >> 2;
    const int qtr = blockIdx.x & 3;
    const int tid = threadIdx.x;

    if (tid < 128) {
        // each thread one float4 of P: 4 partials (MLP=4)
        const float4* src = (const float4*)P4;
        const int base = b * N_OBJ * 2;
        float4 s = make_float4(0.f, 0.f, 0.f, 0.f);
#pragma unroll
        for (int nt = 0; nt < N1TILES; nt++) {
            float4 v = src[nt * 8192 + base + tid];
            s.x += v.x; s.y += v.y; s.z += v.z; s.w += v.w;
        }
        ((float4*)Ps)[tid] = s;
    } else {
        // norm8 layout [b][k][nt]: 16 threads per k, 8 contiguous floats each
        const int t = tid - 128;
        const int k = t >> 4, j = t & 15;
        const float4* src = (const float4*)(norm8 + (size_t)(b * KS + k) * N2TILES + j * 8);
        float4 v0 = src[0], v1 = src[1];
        normS[k * 16 + j] = v0.x + v0.y + v0.z + v0.w + v1.x + v1.y + v1.z + v1.w;
    }
    __syncthreads();
    if (tid < KS) {
        float s = 0.f;
#pragma unroll
        for (int p = 0; p < 16; p++) s += normS[tid * 16 + p];
        invS[tid] = rsqrtf(s);
    }
    __syncthreads();

    if (tid < 128) {
        const float4 i0 = *(const float4*)invS;
        const float4 i1 = *(const float4*)(invS + 4);
        const int m = b * 512 + qtr * 128 + tid;
        const int idx = __ldg(idxs + m);
        const int rem = idx & 4095;
        const int src = rem >> 6, dst = rem & 63;
        const float4* ps = (const float4*)(Ps + src * KS);
        const float4* pd = (const float4*)(Ps + dst * KS);
        float4 s0 = ps[0], s1 = ps[1], d0 = pd[0], d1 = pd[1];
        float4 o0 = make_float4((s0.x + d0.x) * i0.x, (s0.y + d0.y) * i0.y,
                                (s0.z + d0.z) * i0.z, (s0.w + d0.w) * i0.w);
        float4 o1 = make_float4((s1.x + d1.x) * i1.x, (s1.y + d1.y) * i1.y,
                                (s1.z + d1.z) * i1.z, (s1.w + d1.w) * i1.w);
        ((float4*)out)[(size_t)m * 2]     = o0;
        ((float4*)out)[(size_t)m * 2 + 1] = o1;
    }
}

// ---------------------------------------------------------------------------
extern "C" void kernel_launch(void* const* d_in, const int* in_sizes, int n_in,
                              void* d_out, int out_size)
{
    const float* node_feats = (const float*)d_in[0];
    const float* q_feats    = (const float*)d_in[1];
    const int*   indexes    = (const int*)d_in[2];
    const float* W_obj      = (const float*)d_in[3];
    const float* b_obj      = (const float*)d_in[4];
    const float* W_q        = (const float*)d_in[5];
    const float* b_q        = (const float*)d_in[6];
    float* out = (float*)d_out;

    __nv_bfloat16 *nodeB, *wobjB, *qB, *wqB;
    float *qh, *P4, *norm8;
    cudaGetSymbolAddress((void**)&nodeB, g_nodeB);
    cudaGetSymbolAddress((void**)&wobjB, g_WobjB);
    cudaGetSymbolAddress((void**)&qB,    g_qB);
    cudaGetSymbolAddress((void**)&wqB,   g_WqB);
    cudaGetSymbolAddress((void**)&qh,    g_q_h);
    cudaGetSymbolAddress((void**)&P4,    g_P4);
    cudaGetSymbolAddress((void**)&norm8, g_norm8);

    // 1) all fp32 -> bf16 conversions, one launch
    cvt_all_kernel<<<6688, 256>>>(node_feats, W_obj, q_feats, W_q,
                                  nodeB, wobjB, qB, wqB);

    // 2) GEMM2 + norm partials (must precede GEMM1: epilogue consumes q_h)
    {
        constexpr int SM = 3 * (64 * 72 * 2 + 64 * 40 * 2);      // 43008
        cudaFuncSetAttribute(gemm2_kernel, cudaFuncAttributeMaxDynamicSharedMemorySize, SM);
        gemm2_kernel<<<N2TILES, 128, SM>>>(qB, wqB, b_q, qh, norm8);
    }
    // 3) GEMM1 (BN=128, 4-stage) fused with P contraction
    {
        constexpr int SM = 4 * (128 * 72 * 2 + 64 * 136 * 2);    // 143360
        cudaFuncSetAttribute(gemm1_kernel, cudaFuncAttributeMaxDynamicSharedMemorySize, SM);
        gemm1_kernel<<<dim3(HID / 128, 4096 / 128), 256, SM>>>(nodeB, wobjB, b_obj, qh, P4);
    }
    // 4) fused finalize + edge gather (4 blocks per batch)
    finalize_gather_kernel<<<4 * B_IMG, 256>>>(indexes, P4, norm8, out);
}